// round 4
// baseline (speedup 1.0000x reference)
#include <cuda_runtime.h>

// DenseQConv1D analytic collapse (exact):
//   out[b,c,l] = cos(theta[c,0]) * (S_even - S_odd) / max(S_total, 1e-24)
//   with S_* = windowed 8-tap sums of a[b,l] = sum_cin x[b,cin,l]^2.
// Derivation: out = s^T (E R) S (E R)^T s ; R S R^T = H(theta0) (x) I^8 ;
// E = CNOT-ring permutation (linear over GF(2)); conjugated M_c is
// diag(+/-cos(theta[c,0])) on the 128-dim patch support, sign = (-1)^(j&1).
//
// R4: warp-self-sufficient phase 1 — window taps assembled via shfl from
//     (main, halo) registers, no STS/LDS on the critical path; 4-way
//     accumulator tree; smem only for the 16 cos values (bar overlapped).

#define BB 8
#define C_IN 16
#define C_OUT 16
#define LL 1024
#define KK 8
#define L_OUT (LL - KK + 1)   // 1017
#define TL 128                // l-positions per block (4 warps x 32)
#define NQ 9
#define FULL 0xFFFFFFFFu

__global__ __launch_bounds__(TL) void DenseQConv1D_84542136255139_kernel(
    const float* __restrict__ x,      // [B, C_IN, L]
    const float* __restrict__ theta,  // [C_OUT, NQ]
    float* __restrict__ out)          // [B, C_OUT, L_OUT]
{
    __shared__ float cosv[C_OUT];

    const int b    = blockIdx.y;
    const int l0   = blockIdx.x * TL;
    const int tid  = threadIdx.x;
    const int lane = tid & 31;

    // Threads 0..15 produce the per-channel cos; consumed only after the
    // load latency below, so the barrier wait is fully overlapped.
    if (tid < C_OUT) cosv[tid] = cosf(theta[tid * NQ]);

    // Phase 1 (per-warp independent): each lane computes
    //   a_main = sum_c x[b,c,l]^2           at l = l0 + tid   (always < LL)
    //   a_halo = sum_c x[b,c,l+32]^2        (lanes 0..6, guarded at the edge)
    const int l = l0 + tid;
    const bool halo_ok = (lane < KK - 1) && (l + 32 < LL);
    const float* xb = x + (size_t)b * (C_IN * LL) + l;

    float m0 = 0.f, m1 = 0.f, m2 = 0.f, m3 = 0.f;
    float h0 = 0.f, h1 = 0.f, h2 = 0.f, h3 = 0.f;
    #pragma unroll
    for (int c = 0; c < C_IN; c += 4) {
        float v0 = xb[(c + 0) * LL];
        float v1 = xb[(c + 1) * LL];
        float v2 = xb[(c + 2) * LL];
        float v3 = xb[(c + 3) * LL];
        float w0 = halo_ok ? xb[(c + 0) * LL + 32] : 0.f;
        float w1 = halo_ok ? xb[(c + 1) * LL + 32] : 0.f;
        float w2 = halo_ok ? xb[(c + 2) * LL + 32] : 0.f;
        float w3 = halo_ok ? xb[(c + 3) * LL + 32] : 0.f;
        m0 = fmaf(v0, v0, m0);  m1 = fmaf(v1, v1, m1);
        m2 = fmaf(v2, v2, m2);  m3 = fmaf(v3, v3, m3);
        h0 = fmaf(w0, w0, h0);  h1 = fmaf(w1, w1, h1);
        h2 = fmaf(w2, w2, h2);  h3 = fmaf(w3, w3, h3);
    }
    const float a_main = (m0 + m1) + (m2 + m3);
    const float a_halo = (h0 + h1) + (h2 + h3);

    // Window taps a[lane+k], k=0..7, from within the warp's 39-value window:
    // idx < 32 -> a_main of lane idx; idx >= 32 -> a_halo of lane idx-32.
    float v[KK];
    v[0] = a_main;
    #pragma unroll
    for (int k = 1; k < KK; ++k) {
        int idx = lane + k;
        float vm = __shfl_sync(FULL, a_main, idx & 31);
        float vh = __shfl_sync(FULL, a_halo, idx & 31);
        v[k] = (idx < 32) ? vm : vh;
    }

    float se = (v[0] + v[2]) + (v[4] + v[6]);
    float so = (v[1] + v[3]) + (v[5] + v[7]);
    float r  = __fdividef(se - so, fmaxf(se + so, 1e-24f));

    __syncthreads();   // cosv ready (long since); cheap at nw=4

    if (l < L_OUT) {
        float* ob = out + (size_t)b * (C_OUT * L_OUT) + l;
        #pragma unroll
        for (int c = 0; c < C_OUT; ++c) {
            ob[c * L_OUT] = cosv[c] * r;
        }
    }
}

extern "C" void kernel_launch(void* const* d_in, const int* in_sizes, int n_in,
                              void* d_out, int out_size)
{
    // Resolve inputs by element count (robust to metadata ordering):
    //   x: 131072, theta: 144, entangle: 262144 (unused)
    const float* x = nullptr;
    const float* theta = nullptr;
    for (int i = 0; i < n_in; ++i) {
        if (in_sizes[i] == BB * C_IN * LL)      x     = (const float*)d_in[i];
        else if (in_sizes[i] == C_OUT * NQ)     theta = (const float*)d_in[i];
    }

    dim3 grid((L_OUT + TL - 1) / TL, BB);   // 8 x 8 = 64 CTAs
    DenseQConv1D_84542136255139_kernel<<<grid, TL>>>(x, theta, (float*)d_out);
}